// round 9
// baseline (speedup 1.0000x reference)
#include <cuda_runtime.h>
#include <cuda_fp16.h>
#include <math.h>
#include <stdint.h>

// Problem constants
#define B_SZ   2
#define T_SEQ  2048
#define C_DIM  1024
#define C3     3072
#define NH     16
#define DH     64
#define MEMLEN 1024
#define M_TOT  4096
#define KD     1024

// Scratch fp16 hi/lo planes (no cudaMalloc allowed)
__device__ __half g_xh[(size_t)M_TOT * KD];
__device__ __half g_xl[(size_t)M_TOT * KD];
__device__ __half g_wqh[(size_t)C3 * KD];
__device__ __half g_wql[(size_t)C3 * KD];
__device__ __half g_wph[(size_t)C_DIM * KD];
__device__ __half g_wpl[(size_t)C_DIM * KD];
__device__ __half g_qkvh[(size_t)M_TOT * C3];
__device__ __half g_qkvl[(size_t)M_TOT * C3];
__device__ __half g_yh[(size_t)M_TOT * KD];

// ---------------------------------------------------------------------------
// helpers
// ---------------------------------------------------------------------------
__device__ __forceinline__ uint32_t pk2(__half a, __half b) {
    __half2 t = __halves2half2(a, b);
    return *reinterpret_cast<uint32_t*>(&t);
}

__device__ __forceinline__ uint32_t pkh(float a, float b) {
    __half2 t = __floats2half2_rn(a, b);
    return *reinterpret_cast<uint32_t*>(&t);
}

__device__ __forceinline__ uint32_t pkf(float a, float b, uint32_t* lo) {
    __half ha = __float2half_rn(a), hb = __float2half_rn(b);
    __half la = __float2half_rn(a - __half2float(ha));
    __half lb = __float2half_rn(b - __half2float(hb));
    *lo = pk2(la, lb);
    return pk2(ha, hb);
}

__device__ __forceinline__ void ldm4(uint32_t r[4], uint32_t a) {
    asm volatile("ldmatrix.sync.aligned.m8n8.x4.shared.b16 {%0,%1,%2,%3},[%4];\n"
                 : "=r"(r[0]), "=r"(r[1]), "=r"(r[2]), "=r"(r[3]) : "r"(a));
}
__device__ __forceinline__ void ldm4t(uint32_t r[4], uint32_t a) {
    asm volatile("ldmatrix.sync.aligned.m8n8.x4.trans.shared.b16 {%0,%1,%2,%3},[%4];\n"
                 : "=r"(r[0]), "=r"(r[1]), "=r"(r[2]), "=r"(r[3]) : "r"(a));
}

__device__ __forceinline__ void mma16(float d[4], const uint32_t a[4],
                                      uint32_t b0, uint32_t b1) {
    asm volatile(
        "mma.sync.aligned.m16n8k16.row.col.f32.f16.f16.f32 "
        "{%0,%1,%2,%3},{%4,%5,%6,%7},{%8,%9},{%0,%1,%2,%3};\n"
        : "+f"(d[0]), "+f"(d[1]), "+f"(d[2]), "+f"(d[3])
        : "r"(a[0]), "r"(a[1]), "r"(a[2]), "r"(a[3]), "r"(b0), "r"(b1));
}

__device__ __forceinline__ void cpa16(uint32_t d, const void* g) {
    asm volatile("cp.async.cg.shared.global [%0], [%1], 16;" :: "r"(d), "l"(g) : "memory");
}
__device__ __forceinline__ void cpa_commit() {
    asm volatile("cp.async.commit_group;" ::: "memory");
}
template <int N>
__device__ __forceinline__ void cpa_wait() {
    asm volatile("cp.async.wait_group %0;" :: "n"(N) : "memory");
}

// ---------------------------------------------------------------------------
// Split fp32 -> fp16 hi/lo planes
// ---------------------------------------------------------------------------
__global__ __launch_bounds__(256)
void split_kernel(const float* __restrict__ src,
                  __half* __restrict__ hi,
                  __half* __restrict__ lo, int n8)
{
    int i = blockIdx.x * 256 + threadIdx.x;
    if (i >= n8) return;
    float4 v0 = ((const float4*)src)[2 * i];
    float4 v1 = ((const float4*)src)[2 * i + 1];
    float v[8] = {v0.x, v0.y, v0.z, v0.w, v1.x, v1.y, v1.z, v1.w};
    uint32_t hp[4], lp[4];
#pragma unroll
    for (int j = 0; j < 4; j++)
        hp[j] = pkf(v[2 * j], v[2 * j + 1], &lp[j]);
    ((uint4*)hi)[i] = make_uint4(hp[0], hp[1], hp[2], hp[3]);
    ((uint4*)lo)[i] = make_uint4(lp[0], lp[1], lp[2], lp[3]);
}

// ---------------------------------------------------------------------------
// fp16 split NT GEMM, 128 threads, 4 warps of 64x64 (better LDSM:MMA ratio).
// Blocks with n0 < fullN use 3-mma; others 2-mma.
// ---------------------------------------------------------------------------
#define PLANE        8192
#define STAGE_BYTES  32768
#define NSTAGE       3
#define GEMM_SMEM    (NSTAGE * STAGE_BYTES)
#define NCH          32

__global__ __launch_bounds__(128)
void gemm_fp16_kernel(const __half* __restrict__ Ah,
                      const __half* __restrict__ Al,
                      const __half* __restrict__ Bh,
                      const __half* __restrict__ Bl,
                      float* __restrict__ C,
                      __half* __restrict__ Ch,
                      __half* __restrict__ Cl, int N, int fullN)
{
    extern __shared__ char smem[];
    const uint32_t sbase = (uint32_t)__cvta_generic_to_shared(smem);
    const int tid = threadIdx.x, lane = tid & 31, warp = tid >> 5;
    const int m0 = blockIdx.y * 128, n0 = blockIdx.x * 128;
    const bool full = (n0 < fullN);
    const int mw = warp >> 1, nw = warp & 1;   // 2x2 warps, each 64x64

    // ---- loader: 16 x 16B per thread per stage (4 offsets x 4 planes) ----
    const __half* baseP[4];
    baseP[0] = Ah + (size_t)m0 * KD;
    baseP[1] = Al + (size_t)m0 * KD;
    baseP[2] = Bh + (size_t)n0 * KD;
    baseP[3] = Bl + (size_t)n0 * KD;
    uint32_t soff[4];
    size_t goff[4];
#pragma unroll
    for (int i = 0; i < 4; i++) {
        int c = tid + i * 128;           // 0..511 within a plane
        int r = c >> 2, kc = c & 3;
        soff[i] = (uint32_t)(r * 64 + ((kc ^ ((r >> 1) & 3)) << 4));
        goff[i] = (size_t)r * KD + kc * 8;
    }

    // ---- fragment address precompute ----
    const int ra = lane & 15;
    const int ksel_a = lane >> 4;
    int rowA[4], swzA[4];
#pragma unroll
    for (int f = 0; f < 4; f++) {
        rowA[f] = mw * 64 + f * 16 + ra;
        swzA[f] = (rowA[f] >> 1) & 3;
    }
    const int rb = (lane & 7) + 8 * (lane >> 4);
    const int ksel_b = (lane >> 3) & 1;
    int rowB[4], swzB[4];
#pragma unroll
    for (int g = 0; g < 4; g++) {
        rowB[g] = nw * 64 + g * 16 + rb;
        swzB[g] = (rowB[g] >> 1) & 3;
    }

    float acc[4][8][4] = {};

#pragma unroll
    for (int pt = 0; pt < 2; pt++) {
        uint32_t sb = sbase + pt * STAGE_BYTES;
#pragma unroll
        for (int i = 0; i < 4; i++)
#pragma unroll
            for (int p = 0; p < 4; p++)
                cpa16(sb + p * PLANE + soff[i], baseP[p] + goff[i] + pt * 32);
        cpa_commit();
    }

    for (int t = 0; t < NCH; t++) {
        cpa_wait<1>();
        __syncthreads();

        if (t + 2 < NCH) {
            uint32_t sb = sbase + ((t + 2) % NSTAGE) * STAGE_BYTES;
#pragma unroll
            for (int i = 0; i < 4; i++)
#pragma unroll
                for (int p = 0; p < 4; p++)
                    cpa16(sb + p * PLANE + soff[i], baseP[p] + goff[i] + (t + 2) * 32);
        }
        cpa_commit();

        const uint32_t sb = sbase + (t % NSTAGE) * STAGE_BYTES;
#pragma unroll
        for (int s16 = 0; s16 < 2; s16++) {
            uint32_t ah[4][4], al[4][4];
#pragma unroll
            for (int f = 0; f < 4; f++) {
                uint32_t off = (uint32_t)(rowA[f] * 64 +
                               (((2 * s16 + ksel_a) ^ swzA[f]) << 4));
                ldm4(ah[f], sb + off);
                if (full) ldm4(al[f], sb + PLANE + off);
            }
#pragma unroll
            for (int g = 0; g < 4; g++) {
                uint32_t offb = (uint32_t)(rowB[g] * 64 +
                                (((2 * s16 + ksel_b) ^ swzB[g]) << 4));
                uint32_t bh[4], bl[4];
                ldm4(bh, sb + 2 * PLANE + offb);
                ldm4(bl, sb + 3 * PLANE + offb);
#pragma unroll
                for (int f = 0; f < 4; f++) {
#pragma unroll
                    for (int j = 0; j < 2; j++) {
                        float* d = acc[f][g * 2 + j];
                        mma16(d, ah[f], bh[2 * j], bh[2 * j + 1]);
                        mma16(d, ah[f], bl[2 * j], bl[2 * j + 1]);
                        if (full) mma16(d, al[f], bh[2 * j], bh[2 * j + 1]);
                    }
                }
            }
        }
    }

    const int er = lane >> 2, ec = (lane & 3) * 2;
#pragma unroll
    for (int f = 0; f < 4; f++) {
        int r = m0 + mw * 64 + f * 16 + er;
#pragma unroll
        for (int j8 = 0; j8 < 8; j8++) {
            int cc = n0 + nw * 64 + j8 * 8 + ec;
            if (Ch) {
                uint32_t lo0, lo1;
                uint32_t hi0 = pkf(acc[f][j8][0], acc[f][j8][1], &lo0);
                uint32_t hi1 = pkf(acc[f][j8][2], acc[f][j8][3], &lo1);
                *(uint32_t*)(Ch + (size_t)r * N + cc) = hi0;
                *(uint32_t*)(Cl + (size_t)r * N + cc) = lo0;
                *(uint32_t*)(Ch + (size_t)(r + 8) * N + cc) = hi1;
                *(uint32_t*)(Cl + (size_t)(r + 8) * N + cc) = lo1;
            } else {
                *(float2*)(C + (size_t)r * N + cc) =
                    make_float2(acc[f][j8][0], acc[f][j8][1]);
                *(float2*)(C + (size_t)(r + 8) * N + cc) =
                    make_float2(acc[f][j8][2], acc[f][j8][3]);
            }
        }
    }
}

// ---------------------------------------------------------------------------
// fp16 mma flash attention (unchanged from R8): S 3-mma, PV 2-mma.
// ---------------------------------------------------------------------------
#define AQ 128
#define AKV 64
#define QH_OFF   0
#define QL_OFF   16384
#define ST_OFF   32768
#define AST      32768
#define QSC_OFF  (ST_OFF + 2 * AST)
#define ATTN2_SMEM (QSC_OFF + 256)

__global__ __launch_bounds__(256)
void attn_mma2(const float* __restrict__ qm,
               const __half* __restrict__ qkvh,
               const __half* __restrict__ qkvl,
               __half* __restrict__ yh)
{
    extern __shared__ char smem[];
    const uint32_t sb = (uint32_t)__cvta_generic_to_shared(smem);
    float* qsc = (float*)(smem + QSC_OFF);
    const int tid = threadIdx.x, lane = tid & 31, warp = tid >> 5;
    const int qt = blockIdx.x, h = blockIdx.y, b = blockIdx.z;
    const int q0 = qt * AQ;

    if (tid < 64) qsc[tid] = logf(2048.0f) * qm[tid] * rsqrtf(64.0f);

    const __half* kvsrc[8];
    uint32_t kvdst[8];
#pragma unroll
    for (int it = 0; it < 8; it++) {
        int c = tid + it * 256;
        int p = c >> 9, r = (c >> 3) & 63, ch = c & 7;
        const __half* bp = (p & 1) ? qkvl : qkvh;
        int col = ((p >> 1) ? 2 * C_DIM : C_DIM) + h * DH + ch * 8;
        kvsrc[it] = bp + (size_t)(b * T_SEQ + r) * C3 + col;
        kvdst[it] = (uint32_t)(p * 8192 + r * 128 + ((ch ^ (r & 7)) << 4));
    }
#pragma unroll
    for (int it = 0; it < 8; it++) cpa16(sb + ST_OFF + kvdst[it], kvsrc[it]);
    cpa_commit();

    __syncthreads();

#pragma unroll
    for (int it = 0; it < 4; it++) {
        int u = tid + it * 256;
        int r = u >> 3, ch = u & 7;
        size_t src = (size_t)(b * T_SEQ + q0 + r) * C3 + h * DH + ch * 8;
        uint4 hv = *(const uint4*)(qkvh + src);
        uint4 lv = *(const uint4*)(qkvl + src);
        const __half2* hp = (const __half2*)&hv;
        const __half2* lp = (const __half2*)&lv;
        uint32_t oh[4], ol[4];
#pragma unroll
        for (int k = 0; k < 4; k++) {
            float2 hf = __half22float2(hp[k]);
            float2 lf = __half22float2(lp[k]);
            float v0 = (hf.x + lf.x) * qsc[ch * 8 + 2 * k];
            float v1 = (hf.y + lf.y) * qsc[ch * 8 + 2 * k + 1];
            oh[k] = pkf(v0, v1, &ol[k]);
        }
        uint32_t off = (uint32_t)(r * 128 + ((ch ^ (r & 7)) << 4));
        *(uint4*)(smem + QH_OFF + off) = make_uint4(oh[0], oh[1], oh[2], oh[3]);
        *(uint4*)(smem + QL_OFF + off) = make_uint4(ol[0], ol[1], ol[2], ol[3]);
    }

    float m0 = -1e30f, m1 = -1e30f, l0 = 0.0f, l1 = 0.0f;
    float acc[8][4] = {};

    const int maxc = (q0 + AQ > MEMLEN) ? (q0 + AQ) : MEMLEN;
    const int nT = maxc / AKV;

    for (int t = 0; t < nT; t++) {
        cpa_wait<0>();
        __syncthreads();
        if (t + 1 < nT) {
            uint32_t stb = sb + ST_OFF + ((t + 1) & 1) * AST;
            size_t delta = (size_t)(t + 1) * AKV * C3;
#pragma unroll
            for (int it = 0; it < 8; it++) cpa16(stb + kvdst[it], kvsrc[it] + delta);
            cpa_commit();
        }
        const uint32_t st = sb + ST_OFF + (t & 1) * AST;

        // ---- S = Q K^T (3-mma fp16) ----
        float s_[8][4] = {};
#pragma unroll
        for (int kk = 0; kk < 4; kk++) {
            uint32_t aH[4], aL[4];
            {
                int row = 16 * warp + (lane & 15);
                int ch = kk * 2 + (lane >> 4);
                uint32_t off = (uint32_t)(row * 128 + ((ch ^ (row & 7)) << 4));
                ldm4(aH, sb + QH_OFF + off);
                ldm4(aL, sb + QL_OFF + off);
            }
#pragma unroll
            for (int jj = 0; jj < 4; jj++) {
                int row = 16 * jj + 8 * (lane >> 4) + (lane & 7);
                int ch = kk * 2 + ((lane >> 3) & 1);
                uint32_t off = (uint32_t)(row * 128 + ((ch ^ (row & 7)) << 4));
                uint32_t bH[4], bL[4];
                ldm4(bH, st + off);
                ldm4(bL, st + 8192 + off);
#pragma unroll
                for (int u = 0; u < 2; u++) {
                    float* d = s_[2 * jj + u];
                    mma16(d, aH, bH[2 * u], bH[2 * u + 1]);
                    mma16(d, aH, bL[2 * u], bL[2 * u + 1]);
                    mma16(d, aL, bH[2 * u], bH[2 * u + 1]);
                }
            }
        }

        const int kj0 = t * AKV;
        if (kj0 >= MEMLEN) {
            int r0g = q0 + 16 * warp + (lane >> 2);
            int cb = kj0 + 2 * (lane & 3);
#pragma unroll
            for (int j = 0; j < 8; j++) {
                int cg = cb + 8 * j;
                if (cg > r0g)         s_[j][0] = -1e30f;
                if (cg + 1 > r0g)     s_[j][1] = -1e30f;
                if (cg > r0g + 8)     s_[j][2] = -1e30f;
                if (cg + 1 > r0g + 8) s_[j][3] = -1e30f;
            }
        }

        // ---- online softmax ----
        float mx0 = -1e30f, mx1 = -1e30f;
#pragma unroll
        for (int j = 0; j < 8; j++) {
            mx0 = fmaxf(mx0, fmaxf(s_[j][0], s_[j][1]));
            mx1 = fmaxf(mx1, fmaxf(s_[j][2], s_[j][3]));
        }
        mx0 = fmaxf(mx0, __shfl_xor_sync(0xffffffffu, mx0, 1));
        mx0 = fmaxf(mx0, __shfl_xor_sync(0xffffffffu, mx0, 2));
        mx1 = fmaxf(mx1, __shfl_xor_sync(0xffffffffu, mx1, 1));
        mx1 = fmaxf(mx1, __shfl_xor_sync(0xffffffffu, mx1, 2));
        float mn0 = fmaxf(m0, mx0), mn1 = fmaxf(m1, mx1);
        float f0 = __expf(m0 - mn0), f1 = __expf(m1 - mn1);
        float sum0 = 0.0f, sum1 = 0.0f;
        uint32_t phA[8], phB[8];
#pragma unroll
        for (int j = 0; j < 8; j++) {
            float p0 = __expf(s_[j][0] - mn0);
            float p1 = __expf(s_[j][1] - mn0);
            float p2 = __expf(s_[j][2] - mn1);
            float p3 = __expf(s_[j][3] - mn1);
            sum0 += p0 + p1; sum1 += p2 + p3;
            phA[j] = pkh(p0, p1);
            phB[j] = pkh(p2, p3);
        }
        sum0 += __shfl_xor_sync(0xffffffffu, sum0, 1);
        sum0 += __shfl_xor_sync(0xffffffffu, sum0, 2);
        sum1 += __shfl_xor_sync(0xffffffffu, sum1, 1);
        sum1 += __shfl_xor_sync(0xffffffffu, sum1, 2);
        l0 = l0 * f0 + sum0; l1 = l1 * f1 + sum1;
        m0 = mn0; m1 = mn1;
#pragma unroll
        for (int j = 0; j < 8; j++) {
            acc[j][0] *= f0; acc[j][1] *= f0;
            acc[j][2] *= f1; acc[j][3] *= f1;
        }

        // ---- P @ V (2-mma: P single fp16, V hi/lo) ----
#pragma unroll
        for (int jj = 0; jj < 4; jj++) {
            uint32_t pa[4] = {phA[2*jj], phB[2*jj], phA[2*jj+1], phB[2*jj+1]};
#pragma unroll
            for (int nn = 0; nn < 4; nn++) {
                int row = 16 * jj + 8 * ((lane >> 3) & 1) + (lane & 7);
                int ch = 2 * nn + (lane >> 4);
                uint32_t off = (uint32_t)(row * 128 + ((ch ^ (row & 7)) << 4));
                uint32_t vH[4], vL[4];
                ldm4t(vH, st + 16384 + off);
                ldm4t(vL, st + 24576 + off);
#pragma unroll
                for (int u = 0; u < 2; u++) {
                    float* d = acc[2 * nn + u];
                    mma16(d, pa, vH[2 * u], vH[2 * u + 1]);
                    mma16(d, pa, vL[2 * u], vL[2 * u + 1]);
                }
            }
        }
    }

    // ---- epilogue ----
    {
        float i0 = 1.0f / l0, i1 = 1.0f / l1;
        size_t r0 = (size_t)(b * T_SEQ + q0 + 16 * warp + (lane >> 2));
        int cb = h * DH + 2 * (lane & 3);
#pragma unroll
        for (int j = 0; j < 8; j++) {
            int cc = cb + 8 * j;
            *(uint32_t*)(yh + r0 * C_DIM + cc)       = pkh(acc[j][0] * i0, acc[j][1] * i0);
            *(uint32_t*)(yh + (r0 + 8) * C_DIM + cc) = pkh(acc[j][2] * i1, acc[j][3] * i1);
        }
    }
}

// ---------------------------------------------------------------------------
// Launch
// ---------------------------------------------------------------------------
extern "C" void kernel_launch(void* const* d_in, const int* in_sizes, int n_in,
                              void* d_out, int out_size)
{
    const float* x      = (const float*)d_in[0];
    const float* w_qkv  = (const float*)d_in[1];
    const float* w_proj = (const float*)d_in[2];
    const float* qm     = (const float*)d_in[3];
    float* out = (float*)d_out;

    static __half *p_xh = nullptr, *p_xl, *p_wqh, *p_wql, *p_wph, *p_wpl;
    static __half *p_qkvh, *p_qkvl, *p_yh;
    if (!p_xh) {
        cudaGetSymbolAddress((void**)&p_xh, g_xh);
        cudaGetSymbolAddress((void**)&p_xl, g_xl);
        cudaGetSymbolAddress((void**)&p_wqh, g_wqh);
        cudaGetSymbolAddress((void**)&p_wql, g_wql);
        cudaGetSymbolAddress((void**)&p_wph, g_wph);
        cudaGetSymbolAddress((void**)&p_wpl, g_wpl);
        cudaGetSymbolAddress((void**)&p_qkvh, g_qkvh);
        cudaGetSymbolAddress((void**)&p_qkvl, g_qkvl);
        cudaGetSymbolAddress((void**)&p_yh, g_yh);
        cudaFuncSetAttribute(gemm_fp16_kernel,
                             cudaFuncAttributeMaxDynamicSharedMemorySize, GEMM_SMEM);
        cudaFuncSetAttribute(attn_mma2,
                             cudaFuncAttributeMaxDynamicSharedMemorySize, ATTN2_SMEM);
    }

    // Split fp32 inputs into fp16 hi/lo planes
    split_kernel<<<(M_TOT * KD / 8 + 255) / 256, 256>>>(x, p_xh, p_xl, M_TOT * KD / 8);
    split_kernel<<<(C3 * KD / 8 + 255) / 256, 256>>>(w_qkv, p_wqh, p_wql, C3 * KD / 8);
    split_kernel<<<(C_DIM * KD / 8 + 255) / 256, 256>>>(w_proj, p_wph, p_wpl, C_DIM * KD / 8);

    // GEMM1: qkv = x @ w_qkv^T -> fp16 hi/lo planes (Q,K 3-mma; V 2-mma)
    {
        dim3 grid(C3 / 128, M_TOT / 128);
        gemm_fp16_kernel<<<grid, 128, GEMM_SMEM>>>(p_xh, p_xl, p_wqh, p_wql,
                                                   nullptr, p_qkvh, p_qkvl, C3,
                                                   2 * C_DIM);
    }

    // Fused attention -> y single fp16 plane
    {
        dim3 grid(T_SEQ / AQ, NH, B_SZ);
        attn_mma2<<<grid, 256, ATTN2_SMEM>>>(qm, p_qkvh, p_qkvl, p_yh);
    }

    // GEMM2: out = y @ w_proj^T -> fp32, 2-mma everywhere
    {
        dim3 grid(C_DIM / 128, M_TOT / 128);
        gemm_fp16_kernel<<<grid, 128, GEMM_SMEM>>>(p_yh, p_yh, p_wph, p_wpl,
                                                   out, nullptr, nullptr, C_DIM, 0);
    }
}